// round 11
// baseline (speedup 1.0000x reference)
#include <cuda_runtime.h>
#include <cuda_fp16.h>
#include <cstdint>

// ---------------- problem constants ----------------
constexpr int Bb   = 4;
constexpr int Ts   = 2048;
constexpr int Cc   = 1024;
constexpr int Hh   = 16;
constexpr int Dh   = 64;
constexpr int Mtot = Bb * Ts;      // 8192
constexpr int Nqkv = 3 * Cc;       // 3072
constexpr int Kd   = Cc;           // 1024

// ---------------- scratch (device globals) ----------------
__device__ float g_qkv[(size_t)Mtot * Nqkv];
__device__ __align__(1024) __half g_x_h[(size_t)Mtot * Kd];   // x hi  [M][K]
__device__ __align__(1024) __half g_x_l[(size_t)Mtot * Kd];
__device__ __align__(1024) __half g_wq_h[(size_t)Nqkv * Kd];  // w_qkv^T hi [N][K]
__device__ __align__(1024) __half g_wq_l[(size_t)Nqkv * Kd];
__device__ __align__(1024) __half g_wo_h[(size_t)Cc * Kd];    // w_out^T hi [N][K]
__device__ __align__(1024) __half g_wo_l[(size_t)Cc * Kd];
__device__ __align__(1024) __half g_a_h[(size_t)Mtot * Kd];   // attn out hi [M][K]
__device__ __align__(1024) __half g_a_l[(size_t)Mtot * Kd];
// attention operands, per-head layouts
__device__ __align__(1024) __half g_q_h[(size_t)Bb * Hh * Ts * Dh];   // [b,h,t,d] (pre-scaled)
__device__ __align__(1024) __half g_q_l[(size_t)Bb * Hh * Ts * Dh];
__device__ __align__(1024) __half g_k_h[(size_t)Bb * Hh * Ts * Dh];   // [b,h,t,d]
__device__ __align__(1024) __half g_k_l[(size_t)Bb * Hh * Ts * Dh];
__device__ __align__(1024) __half g_vt_h[(size_t)Bb * Hh * Dh * Ts];  // [b,h,d,t]
__device__ __align__(1024) __half g_vt_l[(size_t)Bb * Hh * Dh * Ts];

// ---------------- PTX helpers (sm_80-level, compile for compute_103) --------
__device__ __forceinline__ uint32_t smem_u32(const void* p) {
    uint32_t a;
    asm("{ .reg .u64 t; cvta.to.shared.u64 t, %1; cvt.u32.u64 %0, t; }" : "=r"(a) : "l"(p));
    return a;
}
__device__ __forceinline__ void cpa16(uint32_t dst, const void* src) {
    asm volatile("cp.async.cg.shared.global [%0], [%1], 16;" :: "r"(dst), "l"(src));
}
__device__ __forceinline__ void cp_commit() {
    asm volatile("cp.async.commit_group;" ::: "memory");
}
template<int n>
__device__ __forceinline__ void cp_wait() {
    asm volatile("cp.async.wait_group %0;" :: "n"(n) : "memory");
}
__device__ __forceinline__ void ldsm4(uint32_t* r, uint32_t addr) {
    asm volatile("ldmatrix.sync.aligned.m8n8.x4.shared.b16 {%0,%1,%2,%3}, [%4];"
                 : "=r"(r[0]), "=r"(r[1]), "=r"(r[2]), "=r"(r[3]) : "r"(addr));
}
__device__ __forceinline__ void mma16816(float* d, const uint32_t* a, const uint32_t* b) {
    asm volatile(
        "mma.sync.aligned.m16n8k16.row.col.f32.f16.f16.f32 "
        "{%0,%1,%2,%3}, {%4,%5,%6,%7}, {%8,%9}, {%0,%1,%2,%3};"
        : "+f"(d[0]), "+f"(d[1]), "+f"(d[2]), "+f"(d[3])
        : "r"(a[0]), "r"(a[1]), "r"(a[2]), "r"(a[3]), "r"(b[0]), "r"(b[1]));
}
__device__ __forceinline__ void pack_hilo(float x, float y, uint32_t& h, uint32_t& l) {
    __half2 hh = __floats2half2_rn(x, y);
    float2 hf = __half22float2(hh);
    __half2 ll = __floats2half2_rn(x - hf.x, y - hf.y);
    h = *(uint32_t*)&hh;
    l = *(uint32_t*)&ll;
}

// ---------------------------------------------------------------------------
// conv_A: fp32 [rows,1024] -> hi/lo fp16 row-major (8 elems/thread)
// ---------------------------------------------------------------------------
__global__ __launch_bounds__(256)
void conv_A(const float* __restrict__ src, __half* __restrict__ dh, __half* __restrict__ dl)
{
    size_t u = (size_t)blockIdx.x * 256 + threadIdx.x;
    const float4* p = (const float4*)(src + u * 8);
    float4 f0 = p[0], f1 = p[1];
    float f[8] = {f0.x, f0.y, f0.z, f0.w, f1.x, f1.y, f1.z, f1.w};
    union { __half h[8]; uint4 v; } H, L;
#pragma unroll
    for (int j = 0; j < 8; j++) {
        __half hi = __float2half_rn(f[j]);
        H.h[j] = hi;
        L.h[j] = __float2half_rn(f[j] - __half2float(hi));
    }
    *(uint4*)(dh + u * 8) = H.v;
    *(uint4*)(dl + u * 8) = L.v;
}

// conv_B: fp32 weight [K,N] -> transposed [N][K] hi/lo
__global__ __launch_bounds__(256)
void conv_B(const float* __restrict__ w, __half* __restrict__ dh, __half* __restrict__ dl, int N)
{
    int n  = blockIdx.x * 256 + threadIdx.x;
    int k0 = blockIdx.y * 8;
    union { __half h[8]; uint4 v; } H, L;
#pragma unroll
    for (int j = 0; j < 8; j++) {
        float f = w[(size_t)(k0 + j) * N + n];
        __half hi = __float2half_rn(f);
        H.h[j] = hi;
        L.h[j] = __float2half_rn(f - __half2float(hi));
    }
    *(uint4*)(dh + (size_t)n * Kd + k0) = H.v;
    *(uint4*)(dl + (size_t)n * Kd + k0) = L.v;
}

// ---------------------------------------------------------------------------
// conv_qkv: g_qkv fp32 -> Q(hi/lo, pre-scaled) [b,h,t,d], K(hi/lo) [b,h,t,d],
//           V^T(hi/lo) [b,h,d,t].  grid (Ts/64, Hh, Bb), 256 thr.
// ---------------------------------------------------------------------------
__global__ __launch_bounds__(256)
void conv_qkv()
{
    __shared__ float vs[64][65];
    const int b = blockIdx.z, h = blockIdx.y, t0 = blockIdx.x * 64;
    const int tid = threadIdx.x;
    const int tl = tid >> 2;
    const int d0 = (tid & 3) * 16;
    const float* src = g_qkv + ((size_t)b * Ts + t0 + tl) * Nqkv + h * Dh + d0;
    const size_t qk_off = ((size_t)(b * Hh + h) * Ts + t0 + tl) * Dh + d0;

    union { __half hh[16]; uint4 v[2]; } QH_, QL_, KH_, KL_;
#pragma unroll
    for (int j = 0; j < 16; j++) {
        float q = src[j] * 0.125f;
        __half qh = __float2half_rn(q);
        QH_.hh[j] = qh;
        QL_.hh[j] = __float2half_rn(q - __half2float(qh));
        float k = src[Cc + j];
        __half kh = __float2half_rn(k);
        KH_.hh[j] = kh;
        KL_.hh[j] = __float2half_rn(k - __half2float(kh));
        vs[tl][d0 + j] = src[2 * Cc + j];
    }
    *(uint4*)(g_q_h + qk_off) = QH_.v[0]; *(uint4*)(g_q_h + qk_off + 8) = QH_.v[1];
    *(uint4*)(g_q_l + qk_off) = QL_.v[0]; *(uint4*)(g_q_l + qk_off + 8) = QL_.v[1];
    *(uint4*)(g_k_h + qk_off) = KH_.v[0]; *(uint4*)(g_k_h + qk_off + 8) = KH_.v[1];
    *(uint4*)(g_k_l + qk_off) = KL_.v[0]; *(uint4*)(g_k_l + qk_off + 8) = KL_.v[1];
    __syncthreads();

    const int d  = tid >> 2;
    const int tg = (tid & 3) * 16;
    union { __half hh[16]; uint4 v[2]; } VH_, VL_;
#pragma unroll
    for (int j = 0; j < 16; j++) {
        float f = vs[tg + j][d];
        __half hi = __float2half_rn(f);
        VH_.hh[j] = hi;
        VL_.hh[j] = __float2half_rn(f - __half2float(hi));
    }
    size_t vt_off = ((size_t)(b * Hh + h) * Dh + d) * Ts + t0 + tg;
    *(uint4*)(g_vt_h + vt_off) = VH_.v[0]; *(uint4*)(g_vt_h + vt_off + 8) = VH_.v[1];
    *(uint4*)(g_vt_l + vt_off) = VL_.v[0]; *(uint4*)(g_vt_l + vt_off + 8) = VL_.v[1];
}

// ---------------------------------------------------------------------------
// HMMA GEMM v2 (unchanged, known-good R10): 128x128, BK=32, 3 stages, 2 blk/SM.
// ---------------------------------------------------------------------------
constexpr int BK2      = 32;
constexpr int T2_BYTES = 128 * BK2 * 2;     // 8 KB per operand tile
constexpr int S2_BYTES = 4 * T2_BYTES;      // 32 KB per stage
constexpr int NST      = 3;
constexpr int GEMM_SMEM = NST * S2_BYTES;   // 98304
constexpr int NCH2     = Kd / BK2;          // 32 chunks

__global__ __launch_bounds__(256, 2)
void gemm_hmma(const __half* __restrict__ Ah, const __half* __restrict__ Al,
               const __half* __restrict__ Bh, const __half* __restrict__ Bl,
               const float* __restrict__ bias, float* __restrict__ C, int N)
{
    extern __shared__ char smem_raw[];
    const uint32_t sbase = smem_u32(smem_raw);

    const int tid  = threadIdx.x;
    const int lane = tid & 31;
    const int wid  = tid >> 5;
    const int wm   = wid >> 2;
    const int wn   = wid & 3;
    const int bm   = blockIdx.y, bn = blockIdx.x;

    const int cr  = tid >> 1;
    const int cu0 = (tid & 1) * 2;
    const int csw = (cr >> 1) & 3;
    const __half* srcs[4] = {
        Ah + (size_t)(bm * 128 + cr) * Kd,
        Al + (size_t)(bm * 128 + cr) * Kd,
        Bh + (size_t)(bn * 128 + cr) * Kd,
        Bl + (size_t)(bn * 128 + cr) * Kd
    };
    const uint32_t dstrow = (uint32_t)cr * 64;

    auto load_stage = [&](int s, int ch) {
        uint32_t sb = sbase + s * S2_BYTES;
#pragma unroll
        for (int t = 0; t < 4; t++) {
            const __half* src = srcs[t] + ch * BK2;
            uint32_t tb = sb + t * T2_BYTES + dstrow;
#pragma unroll
            for (int j = 0; j < 2; j++) {
                int u = cu0 + j;
                cpa16(tb + ((u ^ csw) * 16), src + u * 8);
            }
        }
    };

    float acc[4][4][4];
#pragma unroll
    for (int i = 0; i < 4; i++)
#pragma unroll
        for (int j = 0; j < 4; j++)
#pragma unroll
            for (int k = 0; k < 4; k++) acc[i][j][k] = 0.f;

    const int rA = lane & 15, kg = lane >> 4;
    uint32_t arow[4], brow[2];
    int asw[4], bsw[2];
#pragma unroll
    for (int mi = 0; mi < 4; mi++) {
        int r = wm * 64 + mi * 16 + rA;
        arow[mi] = (uint32_t)r * 64; asw[mi] = (r >> 1) & 3;
    }
#pragma unroll
    for (int np = 0; np < 2; np++) {
        int r = wn * 32 + np * 16 + rA;
        brow[np] = (uint32_t)r * 64; bsw[np] = (r >> 1) & 3;
    }

    load_stage(0, 0); cp_commit();
    load_stage(1, 1); cp_commit();

    for (int i = 0; i < NCH2; i++) {
        if (i + 2 < NCH2) { load_stage((i + 2) % NST, i + 2); cp_commit(); cp_wait<2>(); }
        else if (i + 1 < NCH2) { cp_wait<1>(); }
        else { cp_wait<0>(); }
        __syncthreads();

        uint32_t sb = sbase + (i % NST) * S2_BYTES;
#pragma unroll
        for (int ks = 0; ks < 2; ks++) {
            int kb = ks * 2 + kg;
            uint32_t bh[4][2], bl[4][2];
#pragma unroll
            for (int np = 0; np < 2; np++) {
                uint32_t off = brow[np] + (uint32_t)((kb ^ bsw[np]) * 16);
                uint32_t t[4];
                ldsm4(t, sb + 2 * T2_BYTES + off);
                bh[2*np][0] = t[0]; bh[2*np+1][0] = t[1];
                bh[2*np][1] = t[2]; bh[2*np+1][1] = t[3];
                ldsm4(t, sb + 3 * T2_BYTES + off);
                bl[2*np][0] = t[0]; bl[2*np+1][0] = t[1];
                bl[2*np][1] = t[2]; bl[2*np+1][1] = t[3];
            }
#pragma unroll
            for (int mi = 0; mi < 4; mi++) {
                uint32_t off = arow[mi] + (uint32_t)((kb ^ asw[mi]) * 16);
                uint32_t ah[4], al[4];
                ldsm4(ah, sb + off);
                ldsm4(al, sb + T2_BYTES + off);
#pragma unroll
                for (int ni = 0; ni < 4; ni++) {
                    mma16816(acc[mi][ni], ah, bh[ni]);
                    mma16816(acc[mi][ni], ah, bl[ni]);
                    mma16816(acc[mi][ni], al, bh[ni]);
                }
            }
        }
        __syncthreads();
    }

    const int er = lane >> 2, ec = (lane & 3) * 2;
#pragma unroll
    for (int mi = 0; mi < 4; mi++) {
        size_t r0 = (size_t)bm * 128 + wm * 64 + mi * 16 + er;
#pragma unroll
        for (int ni = 0; ni < 4; ni++) {
            int c = bn * 128 + wn * 32 + ni * 8 + ec;
            float2 bv = *(const float2*)(bias + c);
            float2 o0 = { acc[mi][ni][0] + bv.x, acc[mi][ni][1] + bv.y };
            float2 o1 = { acc[mi][ni][2] + bv.x, acc[mi][ni][3] + bv.y };
            *(float2*)(C + r0 * N + c)       = o0;
            *(float2*)(C + (r0 + 8) * N + c) = o1;
        }
    }
}

// ---------------------------------------------------------------------------
// flash_hmma v2: 512 threads, 256 q-rows per block (16 warps x 16 rows).
// Q smem 64 KB + 2 x 32 KB KV stages = 128 KB. KV traffic halved vs v1.
// Per-warp math identical to v1 (bit-identical numerics).
// ---------------------------------------------------------------------------
constexpr int QROWS    = 256;
constexpr int QSM      = QROWS * 64 * 2;          // 32 KB per Q array
constexpr int ATT_SMEM = 2 * QSM + 2 * 32768;     // 131072

__global__ __launch_bounds__(512, 1)
void flash_hmma()
{
    extern __shared__ char sm[];
    const uint32_t sb  = smem_u32(sm);
    const uint32_t QHs = sb, QLs = sb + QSM;
    const uint32_t KVB = sb + 2 * QSM;

    const int tid = threadIdx.x, lane = tid & 31, wq = tid >> 5;  // wq 0..15
    const int qt = blockIdx.x, h = blockIdx.y, b = blockIdx.z;
    const int q0 = qt * QROWS;
    const int ktmax = 4 * qt + 3;

    const size_t bh = (size_t)(b * Hh + h);
    const __half* Qh = g_q_h + (bh * Ts + q0) * Dh;
    const __half* Ql = g_q_l + (bh * Ts + q0) * Dh;
    const __half* Kh = g_k_h + bh * Ts * Dh;
    const __half* Kl = g_k_l + bh * Ts * Dh;
    const __half* Vh = g_vt_h + bh * Dh * Ts;
    const __half* Vl = g_vt_l + bh * Dh * Ts;

    // Q tile loads: 256 rows x 8 units, hi+lo (8 cpa16/thread)
    {
        int qr = tid >> 1, u0 = (tid & 1) * 4;
#pragma unroll
        for (int j = 0; j < 4; j++) {
            int u = u0 + j; int ph = u ^ (qr & 7);
            cpa16(QHs + qr * 128 + ph * 16, Qh + (size_t)qr * 64 + u * 8);
            cpa16(QLs + qr * 128 + ph * 16, Ql + (size_t)qr * 64 + u * 8);
        }
    }
    // KV stage loads: 64 rows x 8 units x 4 arrays (1 cpa16/array/thread)
    const int kr = tid >> 3, ku = tid & 7;
    auto load_kv = [&](int s, int kt) {
        uint32_t base = KVB + s * 32768;
        int k0 = kt * 64;
        int ph = ku ^ (kr & 7);
        uint32_t o = kr * 128 + ph * 16;
        cpa16(base + o,         Kh + (size_t)(k0 + kr) * 64 + ku * 8);
        cpa16(base + 8192 + o,  Kl + (size_t)(k0 + kr) * 64 + ku * 8);
        cpa16(base + 16384 + o, Vh + (size_t)kr * Ts + k0 + ku * 8);
        cpa16(base + 24576 + o, Vl + (size_t)kr * Ts + k0 + ku * 8);
    };
    load_kv(0, 0);
    cp_commit();
    load_kv(1, 1);          // ktmax >= 3 always
    cp_commit();
    cp_wait<1>();
    __syncthreads();

    // Q fragments (A operand), resident for the whole block
    uint32_t qfh[4][4], qfl[4][4];
    {
        int row = wq * 16 + (lane & 15);
#pragma unroll
        for (int ks = 0; ks < 4; ks++) {
            int u = ks * 2 + (lane >> 4); int ph = u ^ (row & 7);
            uint32_t o = row * 128 + ph * 16;
            ldsm4(qfh[ks], QHs + o);
            ldsm4(qfl[ks], QLs + o);
        }
    }

    float m0 = -1e30f, m1 = -1e30f, l0 = 0.f, l1 = 0.f;
    float oacc[8][4];
#pragma unroll
    for (int i = 0; i < 8; i++)
#pragma unroll
        for (int j = 0; j < 4; j++) oacc[i][j] = 0.f;

    const int rg0 = q0 + wq * 16 + (lane >> 2);

    for (int kt = 0; kt <= ktmax; kt++) {
        if (kt > 0) {
            if (kt + 1 <= ktmax) { load_kv((kt + 1) & 1, kt + 1); cp_commit(); cp_wait<1>(); }
            else                 { cp_wait<0>(); }
            __syncthreads();
        }
        const uint32_t kb = KVB + (kt & 1) * 32768;
        const int k0 = kt * 64;

        if (k0 <= q0 + wq * 16 + 15) {
            float sacc[8][4];
#pragma unroll
            for (int i = 0; i < 8; i++)
#pragma unroll
                for (int j = 0; j < 4; j++) sacc[i][j] = 0.f;

#pragma unroll
            for (int ks = 0; ks < 4; ks++) {
#pragma unroll
                for (int np = 0; np < 4; np++) {
                    int row = np * 16 + (lane & 15);
                    int u = ks * 2 + (lane >> 4); int ph = u ^ (row & 7);
                    uint32_t o = row * 128 + ph * 16;
                    uint32_t th[4], tl[4];
                    ldsm4(th, kb + o);
                    ldsm4(tl, kb + 8192 + o);
                    uint32_t beh[2] = {th[0], th[2]}, boh[2] = {th[1], th[3]};
                    uint32_t bel[2] = {tl[0], tl[2]}, bol[2] = {tl[1], tl[3]};
                    mma16816(sacc[2*np],   qfh[ks], beh);
                    mma16816(sacc[2*np],   qfh[ks], bel);
                    mma16816(sacc[2*np],   qfl[ks], beh);
                    mma16816(sacc[2*np+1], qfh[ks], boh);
                    mma16816(sacc[2*np+1], qfh[ks], bol);
                    mma16816(sacc[2*np+1], qfl[ks], boh);
                }
            }
            if (k0 + 63 > q0 + wq * 16) {
#pragma unroll
                for (int nt = 0; nt < 8; nt++) {
                    int cg = k0 + nt * 8 + (lane & 3) * 2;
                    if (cg     > rg0)     sacc[nt][0] = -1e30f;
                    if (cg + 1 > rg0)     sacc[nt][1] = -1e30f;
                    if (cg     > rg0 + 8) sacc[nt][2] = -1e30f;
                    if (cg + 1 > rg0 + 8) sacc[nt][3] = -1e30f;
                }
            }
            float mx0 = -1e30f, mx1 = -1e30f;
#pragma unroll
            for (int nt = 0; nt < 8; nt++) {
                mx0 = fmaxf(mx0, fmaxf(sacc[nt][0], sacc[nt][1]));
                mx1 = fmaxf(mx1, fmaxf(sacc[nt][2], sacc[nt][3]));
            }
            mx0 = fmaxf(mx0, __shfl_xor_sync(0xffffffffu, mx0, 1));
            mx0 = fmaxf(mx0, __shfl_xor_sync(0xffffffffu, mx0, 2));
            mx1 = fmaxf(mx1, __shfl_xor_sync(0xffffffffu, mx1, 1));
            mx1 = fmaxf(mx1, __shfl_xor_sync(0xffffffffu, mx1, 2));
            float mn0 = fmaxf(m0, mx0), mn1 = fmaxf(m1, mx1);
            float f0 = __expf(m0 - mn0), f1 = __expf(m1 - mn1);
            m0 = mn0; m1 = mn1;
            float rs0 = 0.f, rs1 = 0.f;
#pragma unroll
            for (int nt = 0; nt < 8; nt++) {
                sacc[nt][0] = __expf(sacc[nt][0] - mn0); rs0 += sacc[nt][0];
                sacc[nt][1] = __expf(sacc[nt][1] - mn0); rs0 += sacc[nt][1];
                sacc[nt][2] = __expf(sacc[nt][2] - mn1); rs1 += sacc[nt][2];
                sacc[nt][3] = __expf(sacc[nt][3] - mn1); rs1 += sacc[nt][3];
            }
            rs0 += __shfl_xor_sync(0xffffffffu, rs0, 1);
            rs0 += __shfl_xor_sync(0xffffffffu, rs0, 2);
            rs1 += __shfl_xor_sync(0xffffffffu, rs1, 1);
            rs1 += __shfl_xor_sync(0xffffffffu, rs1, 2);
            l0 = l0 * f0 + rs0;
            l1 = l1 * f1 + rs1;
#pragma unroll
            for (int dt = 0; dt < 8; dt++) {
                oacc[dt][0] *= f0; oacc[dt][1] *= f0;
                oacc[dt][2] *= f1; oacc[dt][3] *= f1;
            }
#pragma unroll
            for (int ks = 0; ks < 4; ks++) {
                uint32_t pah[4], pal[4];
                pack_hilo(sacc[2*ks][0],   sacc[2*ks][1],   pah[0], pal[0]);
                pack_hilo(sacc[2*ks][2],   sacc[2*ks][3],   pah[1], pal[1]);
                pack_hilo(sacc[2*ks+1][0], sacc[2*ks+1][1], pah[2], pal[2]);
                pack_hilo(sacc[2*ks+1][2], sacc[2*ks+1][3], pah[3], pal[3]);
#pragma unroll
                for (int dp = 0; dp < 4; dp++) {
                    int row = dp * 16 + (lane & 15);
                    int u = ks * 2 + (lane >> 4); int ph = u ^ (row & 7);
                    uint32_t o = row * 128 + ph * 16;
                    uint32_t th[4], tl[4];
                    ldsm4(th, kb + 16384 + o);
                    ldsm4(tl, kb + 24576 + o);
                    uint32_t beh[2] = {th[0], th[2]}, boh[2] = {th[1], th[3]};
                    uint32_t bel[2] = {tl[0], tl[2]}, bol[2] = {tl[1], tl[3]};
                    mma16816(oacc[2*dp],   pah, beh);
                    mma16816(oacc[2*dp],   pah, bel);
                    mma16816(oacc[2*dp],   pal, beh);
                    mma16816(oacc[2*dp+1], pah, boh);
                    mma16816(oacc[2*dp+1], pah, bol);
                    mma16816(oacc[2*dp+1], pal, boh);
                }
            }
        }
        __syncthreads();
    }

    float i0 = 1.f / l0, i1 = 1.f / l1;
#pragma unroll
    for (int dt = 0; dt < 8; dt++) {
        int c = h * Dh + dt * 8 + (lane & 3) * 2;
        uint32_t hh, ll;
        pack_hilo(oacc[dt][0] * i0, oacc[dt][1] * i0, hh, ll);
        size_t off = ((size_t)b * Ts + rg0) * Cc + c;
        *(uint32_t*)(g_a_h + off) = hh;
        *(uint32_t*)(g_a_l + off) = ll;
        pack_hilo(oacc[dt][2] * i1, oacc[dt][3] * i1, hh, ll);
        off = ((size_t)b * Ts + rg0 + 8) * Cc + c;
        *(uint32_t*)(g_a_h + off) = hh;
        *(uint32_t*)(g_a_l + off) = ll;
    }
}

// ---------------------------------------------------------------------------
// Launch (graph-capturable: kernels only)
// ---------------------------------------------------------------------------
extern "C" void kernel_launch(void* const* d_in, const int* in_sizes, int n_in,
                              void* d_out, int out_size)
{
    const float* x     = (const float*)d_in[0];
    const float* w_qkv = (const float*)d_in[1];
    const float* b_qkv = (const float*)d_in[2];
    const float* w_out = (const float*)d_in[3];
    const float* b_out = (const float*)d_in[4];
    float* out = (float*)d_out;

    float* qkv_ptr;
    __half *xh, *xl, *wqh, *wql, *woh, *wol, *ah, *al;
    cudaGetSymbolAddress((void**)&qkv_ptr, g_qkv);
    cudaGetSymbolAddress((void**)&xh,  g_x_h);  cudaGetSymbolAddress((void**)&xl,  g_x_l);
    cudaGetSymbolAddress((void**)&wqh, g_wq_h); cudaGetSymbolAddress((void**)&wql, g_wq_l);
    cudaGetSymbolAddress((void**)&woh, g_wo_h); cudaGetSymbolAddress((void**)&wol, g_wo_l);
    cudaGetSymbolAddress((void**)&ah,  g_a_h);  cudaGetSymbolAddress((void**)&al,  g_a_l);

    cudaFuncSetAttribute(gemm_hmma, cudaFuncAttributeMaxDynamicSharedMemorySize, GEMM_SMEM);
    cudaFuncSetAttribute(flash_hmma, cudaFuncAttributeMaxDynamicSharedMemorySize, ATT_SMEM);

    // 0) operand conversion
    conv_A<<<(int)(((size_t)Mtot * Kd / 8) / 256), 256>>>(x, xh, xl);
    conv_B<<<dim3(Nqkv / 256, Kd / 8), 256>>>(w_qkv, wqh, wql, Nqkv);
    conv_B<<<dim3(Cc / 256, Kd / 8), 256>>>(w_out, woh, wol, Cc);

    // 1) QKV projection (HMMA)
    gemm_hmma<<<dim3(Nqkv / 128, Mtot / 128), 256, GEMM_SMEM>>>(
        xh, xl, wqh, wql, b_qkv, qkv_ptr, Nqkv);

    // 2) per-head hi/lo conversion + V transpose
    conv_qkv<<<dim3(Ts / 64, Hh, Bb), 256>>>();

    // 3) causal flash attention (HMMA), 256 q-rows/block
    flash_hmma<<<dim3(Ts / QROWS, Hh, Bb), 512, ATT_SMEM>>>();

    // 4) output projection (HMMA)
    gemm_hmma<<<dim3(Cc / 128, Mtot / 128), 256, GEMM_SMEM>>>(
        ah, al, woh, wol, b_out, out, Cc);
}

// round 12
// speedup vs baseline: 1.0391x; 1.0391x over previous
#include <cuda_runtime.h>
#include <cuda_fp16.h>
#include <cstdint>

// ---------------- problem constants ----------------
constexpr int Bb   = 4;
constexpr int Ts   = 2048;
constexpr int Cc   = 1024;
constexpr int Hh   = 16;
constexpr int Dh   = 64;
constexpr int Mtot = Bb * Ts;      // 8192
constexpr int Nqkv = 3 * Cc;       // 3072
constexpr int Kd   = Cc;           // 1024

// ---------------- scratch (device globals) ----------------
__device__ float g_qkv[(size_t)Mtot * Nqkv];
__device__ __align__(1024) __half g_x_h[(size_t)Mtot * Kd];   // x hi  [M][K]
__device__ __align__(1024) __half g_x_l[(size_t)Mtot * Kd];
__device__ __align__(1024) __half g_wq_h[(size_t)Nqkv * Kd];  // w_qkv^T hi [N][K]
__device__ __align__(1024) __half g_wq_l[(size_t)Nqkv * Kd];
__device__ __align__(1024) __half g_wo_h[(size_t)Cc * Kd];    // w_out^T hi [N][K]
__device__ __align__(1024) __half g_wo_l[(size_t)Cc * Kd];
__device__ __align__(1024) __half g_a_h[(size_t)Mtot * Kd];   // attn out hi [M][K]
__device__ __align__(1024) __half g_a_l[(size_t)Mtot * Kd];
// attention operands, per-head layouts
__device__ __align__(1024) __half g_q_h[(size_t)Bb * Hh * Ts * Dh];   // [b,h,t,d] (pre-scaled)
__device__ __align__(1024) __half g_q_l[(size_t)Bb * Hh * Ts * Dh];
__device__ __align__(1024) __half g_k_h[(size_t)Bb * Hh * Ts * Dh];   // [b,h,t,d]
__device__ __align__(1024) __half g_k_l[(size_t)Bb * Hh * Ts * Dh];
__device__ __align__(1024) __half g_vt_h[(size_t)Bb * Hh * Dh * Ts];  // [b,h,d,t]
__device__ __align__(1024) __half g_vt_l[(size_t)Bb * Hh * Dh * Ts];

// ---------------- PTX helpers (sm_80-level, compile for compute_103) --------
__device__ __forceinline__ uint32_t smem_u32(const void* p) {
    uint32_t a;
    asm("{ .reg .u64 t; cvta.to.shared.u64 t, %1; cvt.u32.u64 %0, t; }" : "=r"(a) : "l"(p));
    return a;
}
__device__ __forceinline__ void cpa16(uint32_t dst, const void* src) {
    asm volatile("cp.async.cg.shared.global [%0], [%1], 16;" :: "r"(dst), "l"(src));
}
__device__ __forceinline__ void cp_commit() {
    asm volatile("cp.async.commit_group;" ::: "memory");
}
template<int n>
__device__ __forceinline__ void cp_wait() {
    asm volatile("cp.async.wait_group %0;" :: "n"(n) : "memory");
}
__device__ __forceinline__ void ldsm4(uint32_t* r, uint32_t addr) {
    asm volatile("ldmatrix.sync.aligned.m8n8.x4.shared.b16 {%0,%1,%2,%3}, [%4];"
                 : "=r"(r[0]), "=r"(r[1]), "=r"(r[2]), "=r"(r[3]) : "r"(addr));
}
__device__ __forceinline__ void mma16816(float* d, const uint32_t* a, const uint32_t* b) {
    asm volatile(
        "mma.sync.aligned.m16n8k16.row.col.f32.f16.f16.f32 "
        "{%0,%1,%2,%3}, {%4,%5,%6,%7}, {%8,%9}, {%0,%1,%2,%3};"
        : "+f"(d[0]), "+f"(d[1]), "+f"(d[2]), "+f"(d[3])
        : "r"(a[0]), "r"(a[1]), "r"(a[2]), "r"(a[3]), "r"(b[0]), "r"(b[1]));
}
__device__ __forceinline__ void pack_hilo(float x, float y, uint32_t& h, uint32_t& l) {
    __half2 hh = __floats2half2_rn(x, y);
    float2 hf = __half22float2(hh);
    __half2 ll = __floats2half2_rn(x - hf.x, y - hf.y);
    h = *(uint32_t*)&hh;
    l = *(uint32_t*)&ll;
}

// ---------------------------------------------------------------------------
// conv_A: fp32 [rows,1024] -> hi/lo fp16 row-major (8 elems/thread)
// ---------------------------------------------------------------------------
__global__ __launch_bounds__(256)
void conv_A(const float* __restrict__ src, __half* __restrict__ dh, __half* __restrict__ dl)
{
    size_t u = (size_t)blockIdx.x * 256 + threadIdx.x;
    const float4* p = (const float4*)(src + u * 8);
    float4 f0 = p[0], f1 = p[1];
    float f[8] = {f0.x, f0.y, f0.z, f0.w, f1.x, f1.y, f1.z, f1.w};
    union { __half h[8]; uint4 v; } H, L;
#pragma unroll
    for (int j = 0; j < 8; j++) {
        __half hi = __float2half_rn(f[j]);
        H.h[j] = hi;
        L.h[j] = __float2half_rn(f[j] - __half2float(hi));
    }
    *(uint4*)(dh + u * 8) = H.v;
    *(uint4*)(dl + u * 8) = L.v;
}

// conv_B: fp32 weight [K,N] -> transposed [N][K] hi/lo
__global__ __launch_bounds__(256)
void conv_B(const float* __restrict__ w, __half* __restrict__ dh, __half* __restrict__ dl, int N)
{
    int n  = blockIdx.x * 256 + threadIdx.x;
    int k0 = blockIdx.y * 8;
    union { __half h[8]; uint4 v; } H, L;
#pragma unroll
    for (int j = 0; j < 8; j++) {
        float f = w[(size_t)(k0 + j) * N + n];
        __half hi = __float2half_rn(f);
        H.h[j] = hi;
        L.h[j] = __float2half_rn(f - __half2float(hi));
    }
    *(uint4*)(dh + (size_t)n * Kd + k0) = H.v;
    *(uint4*)(dl + (size_t)n * Kd + k0) = L.v;
}

// ---------------------------------------------------------------------------
// conv_qkv: g_qkv fp32 -> Q(hi/lo, pre-scaled) [b,h,t,d], K(hi/lo) [b,h,t,d],
//           V^T(hi/lo) [b,h,d,t].  grid (Ts/64, Hh, Bb), 256 thr.
// ---------------------------------------------------------------------------
__global__ __launch_bounds__(256)
void conv_qkv()
{
    __shared__ float vs[64][65];
    const int b = blockIdx.z, h = blockIdx.y, t0 = blockIdx.x * 64;
    const int tid = threadIdx.x;
    const int tl = tid >> 2;
    const int d0 = (tid & 3) * 16;
    const float* src = g_qkv + ((size_t)b * Ts + t0 + tl) * Nqkv + h * Dh + d0;
    const size_t qk_off = ((size_t)(b * Hh + h) * Ts + t0 + tl) * Dh + d0;

    union { __half hh[16]; uint4 v[2]; } QH_, QL_, KH_, KL_;
#pragma unroll
    for (int j = 0; j < 16; j++) {
        float q = src[j] * 0.125f;
        __half qh = __float2half_rn(q);
        QH_.hh[j] = qh;
        QL_.hh[j] = __float2half_rn(q - __half2float(qh));
        float k = src[Cc + j];
        __half kh = __float2half_rn(k);
        KH_.hh[j] = kh;
        KL_.hh[j] = __float2half_rn(k - __half2float(kh));
        vs[tl][d0 + j] = src[2 * Cc + j];
    }
    *(uint4*)(g_q_h + qk_off) = QH_.v[0]; *(uint4*)(g_q_h + qk_off + 8) = QH_.v[1];
    *(uint4*)(g_q_l + qk_off) = QL_.v[0]; *(uint4*)(g_q_l + qk_off + 8) = QL_.v[1];
    *(uint4*)(g_k_h + qk_off) = KH_.v[0]; *(uint4*)(g_k_h + qk_off + 8) = KH_.v[1];
    *(uint4*)(g_k_l + qk_off) = KL_.v[0]; *(uint4*)(g_k_l + qk_off + 8) = KL_.v[1];
    __syncthreads();

    const int d  = tid >> 2;
    const int tg = (tid & 3) * 16;
    union { __half hh[16]; uint4 v[2]; } VH_, VL_;
#pragma unroll
    for (int j = 0; j < 16; j++) {
        float f = vs[tg + j][d];
        __half hi = __float2half_rn(f);
        VH_.hh[j] = hi;
        VL_.hh[j] = __float2half_rn(f - __half2float(hi));
    }
    size_t vt_off = ((size_t)(b * Hh + h) * Dh + d) * Ts + t0 + tg;
    *(uint4*)(g_vt_h + vt_off) = VH_.v[0]; *(uint4*)(g_vt_h + vt_off + 8) = VH_.v[1];
    *(uint4*)(g_vt_l + vt_off) = VL_.v[0]; *(uint4*)(g_vt_l + vt_off + 8) = VL_.v[1];
}

// ---------------------------------------------------------------------------
// HMMA GEMM v3: identical to v2 except the 12 MMAs per (mi) are pass-major
// (hh x4, hl x4, lh x4) so dependent ops on the same accumulator are 4 apart.
// ---------------------------------------------------------------------------
constexpr int BK2      = 32;
constexpr int T2_BYTES = 128 * BK2 * 2;     // 8 KB per operand tile
constexpr int S2_BYTES = 4 * T2_BYTES;      // 32 KB per stage
constexpr int NST      = 3;
constexpr int GEMM_SMEM = NST * S2_BYTES;   // 98304
constexpr int NCH2     = Kd / BK2;          // 32 chunks

__global__ __launch_bounds__(256, 2)
void gemm_hmma(const __half* __restrict__ Ah, const __half* __restrict__ Al,
               const __half* __restrict__ Bh, const __half* __restrict__ Bl,
               const float* __restrict__ bias, float* __restrict__ C, int N)
{
    extern __shared__ char smem_raw[];
    const uint32_t sbase = smem_u32(smem_raw);

    const int tid  = threadIdx.x;
    const int lane = tid & 31;
    const int wid  = tid >> 5;
    const int wm   = wid >> 2;
    const int wn   = wid & 3;
    const int bm   = blockIdx.y, bn = blockIdx.x;

    const int cr  = tid >> 1;
    const int cu0 = (tid & 1) * 2;
    const int csw = (cr >> 1) & 3;
    const __half* srcs[4] = {
        Ah + (size_t)(bm * 128 + cr) * Kd,
        Al + (size_t)(bm * 128 + cr) * Kd,
        Bh + (size_t)(bn * 128 + cr) * Kd,
        Bl + (size_t)(bn * 128 + cr) * Kd
    };
    const uint32_t dstrow = (uint32_t)cr * 64;

    auto load_stage = [&](int s, int ch) {
        uint32_t sb = sbase + s * S2_BYTES;
#pragma unroll
        for (int t = 0; t < 4; t++) {
            const __half* src = srcs[t] + ch * BK2;
            uint32_t tb = sb + t * T2_BYTES + dstrow;
#pragma unroll
            for (int j = 0; j < 2; j++) {
                int u = cu0 + j;
                cpa16(tb + ((u ^ csw) * 16), src + u * 8);
            }
        }
    };

    float acc[4][4][4];
#pragma unroll
    for (int i = 0; i < 4; i++)
#pragma unroll
        for (int j = 0; j < 4; j++)
#pragma unroll
            for (int k = 0; k < 4; k++) acc[i][j][k] = 0.f;

    const int rA = lane & 15, kg = lane >> 4;
    uint32_t arow[4], brow[2];
    int asw[4], bsw[2];
#pragma unroll
    for (int mi = 0; mi < 4; mi++) {
        int r = wm * 64 + mi * 16 + rA;
        arow[mi] = (uint32_t)r * 64; asw[mi] = (r >> 1) & 3;
    }
#pragma unroll
    for (int np = 0; np < 2; np++) {
        int r = wn * 32 + np * 16 + rA;
        brow[np] = (uint32_t)r * 64; bsw[np] = (r >> 1) & 3;
    }

    load_stage(0, 0); cp_commit();
    load_stage(1, 1); cp_commit();

    for (int i = 0; i < NCH2; i++) {
        if (i + 2 < NCH2) { load_stage((i + 2) % NST, i + 2); cp_commit(); cp_wait<2>(); }
        else if (i + 1 < NCH2) { cp_wait<1>(); }
        else { cp_wait<0>(); }
        __syncthreads();

        uint32_t sb = sbase + (i % NST) * S2_BYTES;
#pragma unroll
        for (int ks = 0; ks < 2; ks++) {
            int kb = ks * 2 + kg;
            uint32_t bh[4][2], bl[4][2];
#pragma unroll
            for (int np = 0; np < 2; np++) {
                uint32_t off = brow[np] + (uint32_t)((kb ^ bsw[np]) * 16);
                uint32_t t[4];
                ldsm4(t, sb + 2 * T2_BYTES + off);
                bh[2*np][0] = t[0]; bh[2*np+1][0] = t[1];
                bh[2*np][1] = t[2]; bh[2*np+1][1] = t[3];
                ldsm4(t, sb + 3 * T2_BYTES + off);
                bl[2*np][0] = t[0]; bl[2*np+1][0] = t[1];
                bl[2*np][1] = t[2]; bl[2*np+1][1] = t[3];
            }
#pragma unroll
            for (int mi = 0; mi < 4; mi++) {
                uint32_t off = arow[mi] + (uint32_t)((kb ^ asw[mi]) * 16);
                uint32_t ah[4], al[4];
                ldsm4(ah, sb + off);
                ldsm4(al, sb + T2_BYTES + off);
                // pass-major: dependent MMAs on the same acc are 4 issues apart
#pragma unroll
                for (int ni = 0; ni < 4; ni++) mma16816(acc[mi][ni], ah, bh[ni]);
#pragma unroll
                for (int ni = 0; ni < 4; ni++) mma16816(acc[mi][ni], ah, bl[ni]);
#pragma unroll
                for (int ni = 0; ni < 4; ni++) mma16816(acc[mi][ni], al, bh[ni]);
            }
        }
        __syncthreads();
    }

    const int er = lane >> 2, ec = (lane & 3) * 2;
#pragma unroll
    for (int mi = 0; mi < 4; mi++) {
        size_t r0 = (size_t)bm * 128 + wm * 64 + mi * 16 + er;
#pragma unroll
        for (int ni = 0; ni < 4; ni++) {
            int c = bn * 128 + wn * 32 + ni * 8 + ec;
            float2 bv = *(const float2*)(bias + c);
            float2 o0 = { acc[mi][ni][0] + bv.x, acc[mi][ni][1] + bv.y };
            float2 o1 = { acc[mi][ni][2] + bv.x, acc[mi][ni][3] + bv.y };
            *(float2*)(C + r0 * N + c)       = o0;
            *(float2*)(C + (r0 + 8) * N + c) = o1;
        }
    }
}

// ---------------------------------------------------------------------------
// flash_hmma: REVERTED to known-good R10 version (256 threads, 128 q-rows).
// ---------------------------------------------------------------------------
constexpr int ATT_SMEM = 32768 + 2 * 32768;  // 98304

__global__ __launch_bounds__(256, 1)
void flash_hmma()
{
    extern __shared__ char sm[];
    const uint32_t sb  = smem_u32(sm);
    const uint32_t QHs = sb, QLs = sb + 16384;

    const int tid = threadIdx.x, lane = tid & 31, wq = tid >> 5;
    const int qt = blockIdx.x, h = blockIdx.y, b = blockIdx.z;
    const int q0 = qt * 128;
    const int ktmax = 2 * qt + 1;

    const size_t bh = (size_t)(b * Hh + h);
    const __half* Qh = g_q_h + (bh * Ts + q0) * Dh;
    const __half* Ql = g_q_l + (bh * Ts + q0) * Dh;
    const __half* Kh = g_k_h + bh * Ts * Dh;
    const __half* Kl = g_k_l + bh * Ts * Dh;
    const __half* Vh = g_vt_h + bh * Dh * Ts;
    const __half* Vl = g_vt_l + bh * Dh * Ts;

    {
        int qr = tid >> 1, u0 = (tid & 1) * 4;
#pragma unroll
        for (int j = 0; j < 4; j++) {
            int u = u0 + j; int ph = u ^ (qr & 7);
            cpa16(QHs + qr * 128 + ph * 16, Qh + (size_t)qr * 64 + u * 8);
            cpa16(QLs + qr * 128 + ph * 16, Ql + (size_t)qr * 64 + u * 8);
        }
    }
    const int kr = tid >> 2, ku0 = (tid & 3) * 2;
    auto load_kv = [&](int s, int kt) {
        uint32_t base = sb + 32768 + s * 32768;
        int k0 = kt * 64;
#pragma unroll
        for (int j = 0; j < 2; j++) {
            int u = ku0 + j; int ph = u ^ (kr & 7);
            uint32_t o = kr * 128 + ph * 16;
            cpa16(base + o,         Kh + (size_t)(k0 + kr) * 64 + u * 8);
            cpa16(base + 8192 + o,  Kl + (size_t)(k0 + kr) * 64 + u * 8);
            cpa16(base + 16384 + o, Vh + (size_t)kr * Ts + k0 + u * 8);
            cpa16(base + 24576 + o, Vl + (size_t)kr * Ts + k0 + u * 8);
        }
    };
    load_kv(0, 0);
    cp_commit();
    load_kv(1, 1);
    cp_commit();
    cp_wait<1>();
    __syncthreads();

    uint32_t qfh[4][4], qfl[4][4];
    {
        int row = wq * 16 + (lane & 15);
#pragma unroll
        for (int ks = 0; ks < 4; ks++) {
            int u = ks * 2 + (lane >> 4); int ph = u ^ (row & 7);
            uint32_t o = row * 128 + ph * 16;
            ldsm4(qfh[ks], QHs + o);
            ldsm4(qfl[ks], QLs + o);
        }
    }

    float m0 = -1e30f, m1 = -1e30f, l0 = 0.f, l1 = 0.f;
    float oacc[8][4];
#pragma unroll
    for (int i = 0; i < 8; i++)
#pragma unroll
        for (int j = 0; j < 4; j++) oacc[i][j] = 0.f;

    const int rg0 = q0 + wq * 16 + (lane >> 2);

    for (int kt = 0; kt <= ktmax; kt++) {
        if (kt > 0) {
            if (kt + 1 <= ktmax) { load_kv((kt + 1) & 1, kt + 1); cp_commit(); cp_wait<1>(); }
            else                 { cp_wait<0>(); }
            __syncthreads();
        }
        const uint32_t kb = sb + 32768 + (kt & 1) * 32768;
        const int k0 = kt * 64;

        if (k0 <= q0 + wq * 16 + 15) {
            float sacc[8][4];
#pragma unroll
            for (int i = 0; i < 8; i++)
#pragma unroll
                for (int j = 0; j < 4; j++) sacc[i][j] = 0.f;

#pragma unroll
            for (int ks = 0; ks < 4; ks++) {
#pragma unroll
                for (int np = 0; np < 4; np++) {
                    int row = np * 16 + (lane & 15);
                    int u = ks * 2 + (lane >> 4); int ph = u ^ (row & 7);
                    uint32_t o = row * 128 + ph * 16;
                    uint32_t th[4], tl[4];
                    ldsm4(th, kb + o);
                    ldsm4(tl, kb + 8192 + o);
                    uint32_t beh[2] = {th[0], th[2]}, boh[2] = {th[1], th[3]};
                    uint32_t bel[2] = {tl[0], tl[2]}, bol[2] = {tl[1], tl[3]};
                    mma16816(sacc[2*np],   qfh[ks], beh);
                    mma16816(sacc[2*np],   qfh[ks], bel);
                    mma16816(sacc[2*np],   qfl[ks], beh);
                    mma16816(sacc[2*np+1], qfh[ks], boh);
                    mma16816(sacc[2*np+1], qfh[ks], bol);
                    mma16816(sacc[2*np+1], qfl[ks], boh);
                }
            }
            if (k0 + 63 > q0 + wq * 16) {
#pragma unroll
                for (int nt = 0; nt < 8; nt++) {
                    int cg = k0 + nt * 8 + (lane & 3) * 2;
                    if (cg     > rg0)     sacc[nt][0] = -1e30f;
                    if (cg + 1 > rg0)     sacc[nt][1] = -1e30f;
                    if (cg     > rg0 + 8) sacc[nt][2] = -1e30f;
                    if (cg + 1 > rg0 + 8) sacc[nt][3] = -1e30f;
                }
            }
            float mx0 = -1e30f, mx1 = -1e30f;
#pragma unroll
            for (int nt = 0; nt < 8; nt++) {
                mx0 = fmaxf(mx0, fmaxf(sacc[nt][0], sacc[nt][1]));
                mx1 = fmaxf(mx1, fmaxf(sacc[nt][2], sacc[nt][3]));
            }
            mx0 = fmaxf(mx0, __shfl_xor_sync(0xffffffffu, mx0, 1));
            mx0 = fmaxf(mx0, __shfl_xor_sync(0xffffffffu, mx0, 2));
            mx1 = fmaxf(mx1, __shfl_xor_sync(0xffffffffu, mx1, 1));
            mx1 = fmaxf(mx1, __shfl_xor_sync(0xffffffffu, mx1, 2));
            float mn0 = fmaxf(m0, mx0), mn1 = fmaxf(m1, mx1);
            float f0 = __expf(m0 - mn0), f1 = __expf(m1 - mn1);
            m0 = mn0; m1 = mn1;
            float rs0 = 0.f, rs1 = 0.f;
#pragma unroll
            for (int nt = 0; nt < 8; nt++) {
                sacc[nt][0] = __expf(sacc[nt][0] - mn0); rs0 += sacc[nt][0];
                sacc[nt][1] = __expf(sacc[nt][1] - mn0); rs0 += sacc[nt][1];
                sacc[nt][2] = __expf(sacc[nt][2] - mn1); rs1 += sacc[nt][2];
                sacc[nt][3] = __expf(sacc[nt][3] - mn1); rs1 += sacc[nt][3];
            }
            rs0 += __shfl_xor_sync(0xffffffffu, rs0, 1);
            rs0 += __shfl_xor_sync(0xffffffffu, rs0, 2);
            rs1 += __shfl_xor_sync(0xffffffffu, rs1, 1);
            rs1 += __shfl_xor_sync(0xffffffffu, rs1, 2);
            l0 = l0 * f0 + rs0;
            l1 = l1 * f1 + rs1;
#pragma unroll
            for (int dt = 0; dt < 8; dt++) {
                oacc[dt][0] *= f0; oacc[dt][1] *= f0;
                oacc[dt][2] *= f1; oacc[dt][3] *= f1;
            }
#pragma unroll
            for (int ks = 0; ks < 4; ks++) {
                uint32_t pah[4], pal[4];
                pack_hilo(sacc[2*ks][0],   sacc[2*ks][1],   pah[0], pal[0]);
                pack_hilo(sacc[2*ks][2],   sacc[2*ks][3],   pah[1], pal[1]);
                pack_hilo(sacc[2*ks+1][0], sacc[2*ks+1][1], pah[2], pal[2]);
                pack_hilo(sacc[2*ks+1][2], sacc[2*ks+1][3], pah[3], pal[3]);
#pragma unroll
                for (int dp = 0; dp < 4; dp++) {
                    int row = dp * 16 + (lane & 15);
                    int u = ks * 2 + (lane >> 4); int ph = u ^ (row & 7);
                    uint32_t o = row * 128 + ph * 16;
                    uint32_t th[4], tl[4];
                    ldsm4(th, kb + 16384 + o);
                    ldsm4(tl, kb + 24576 + o);
                    uint32_t beh[2] = {th[0], th[2]}, boh[2] = {th[1], th[3]};
                    uint32_t bel[2] = {tl[0], tl[2]}, bol[2] = {tl[1], tl[3]};
                    mma16816(oacc[2*dp],   pah, beh);
                    mma16816(oacc[2*dp],   pah, bel);
                    mma16816(oacc[2*dp],   pal, beh);
                    mma16816(oacc[2*dp+1], pah, boh);
                    mma16816(oacc[2*dp+1], pah, bol);
                    mma16816(oacc[2*dp+1], pal, boh);
                }
            }
        }
        __syncthreads();
    }

    float i0 = 1.f / l0, i1 = 1.f / l1;
#pragma unroll
    for (int dt = 0; dt < 8; dt++) {
        int c = h * Dh + dt * 8 + (lane & 3) * 2;
        uint32_t hh, ll;
        pack_hilo(oacc[dt][0] * i0, oacc[dt][1] * i0, hh, ll);
        size_t off = ((size_t)b * Ts + rg0) * Cc + c;
        *(uint32_t*)(g_a_h + off) = hh;
        *(uint32_t*)(g_a_l + off) = ll;
        pack_hilo(oacc[dt][2] * i1, oacc[dt][3] * i1, hh, ll);
        off = ((size_t)b * Ts + rg0 + 8) * Cc + c;
        *(uint32_t*)(g_a_h + off) = hh;
        *(uint32_t*)(g_a_l + off) = ll;
    }
}

// ---------------------------------------------------------------------------
// Launch (graph-capturable: kernels only)
// ---------------------------------------------------------------------------
extern "C" void kernel_launch(void* const* d_in, const int* in_sizes, int n_in,
                              void* d_out, int out_size)
{
    const float* x     = (const float*)d_in[0];
    const float* w_qkv = (const float*)d_in[1];
    const float* b_qkv = (const float*)d_in[2];
    const float* w_out = (const float*)d_in[3];
    const float* b_out = (const float*)d_in[4];
    float* out = (float*)d_out;

    float* qkv_ptr;
    __half *xh, *xl, *wqh, *wql, *woh, *wol, *ah, *al;
    cudaGetSymbolAddress((void**)&qkv_ptr, g_qkv);
    cudaGetSymbolAddress((void**)&xh,  g_x_h);  cudaGetSymbolAddress((void**)&xl,  g_x_l);
    cudaGetSymbolAddress((void**)&wqh, g_wq_h); cudaGetSymbolAddress((void**)&wql, g_wq_l);
    cudaGetSymbolAddress((void**)&woh, g_wo_h); cudaGetSymbolAddress((void**)&wol, g_wo_l);
    cudaGetSymbolAddress((void**)&ah,  g_a_h);  cudaGetSymbolAddress((void**)&al,  g_a_l);

    cudaFuncSetAttribute(gemm_hmma, cudaFuncAttributeMaxDynamicSharedMemorySize, GEMM_SMEM);
    cudaFuncSetAttribute(flash_hmma, cudaFuncAttributeMaxDynamicSharedMemorySize, ATT_SMEM);

    // 0) operand conversion
    conv_A<<<(int)(((size_t)Mtot * Kd / 8) / 256), 256>>>(x, xh, xl);
    conv_B<<<dim3(Nqkv / 256, Kd / 8), 256>>>(w_qkv, wqh, wql, Nqkv);
    conv_B<<<dim3(Cc / 256, Kd / 8), 256>>>(w_out, woh, wol, Cc);

    // 1) QKV projection (HMMA)
    gemm_hmma<<<dim3(Nqkv / 128, Mtot / 128), 256, GEMM_SMEM>>>(
        xh, xl, wqh, wql, b_qkv, qkv_ptr, Nqkv);

    // 2) per-head hi/lo conversion + V transpose
    conv_qkv<<<dim3(Ts / 64, Hh, Bb), 256>>>();

    // 3) causal flash attention (HMMA), 128 q-rows/block
    flash_hmma<<<dim3(Ts / 128, Hh, Bb), 256, ATT_SMEM>>>();

    // 4) output projection (HMMA)
    gemm_hmma<<<dim3(Cc / 128, Mtot / 128), 256, GEMM_SMEM>>>(
        ah, al, woh, wol, b_out, out, Cc);
}

// round 15
// speedup vs baseline: 1.0513x; 1.0118x over previous
#include <cuda_runtime.h>
#include <cuda_fp16.h>
#include <cstdint>

// ---------------- problem constants ----------------
constexpr int Bb   = 4;
constexpr int Ts   = 2048;
constexpr int Cc   = 1024;
constexpr int Hh   = 16;
constexpr int Dh   = 64;
constexpr int Mtot = Bb * Ts;      // 8192
constexpr int Nqkv = 3 * Cc;       // 3072
constexpr int Kd   = Cc;           // 1024

// ---------------- scratch (device globals) ----------------
__device__ float g_qkv[(size_t)Mtot * Nqkv];
__device__ __align__(1024) __half g_x_h[(size_t)Mtot * Kd];   // x hi  [M][K]
__device__ __align__(1024) __half g_x_l[(size_t)Mtot * Kd];
__device__ __align__(1024) __half g_wq_h[(size_t)Nqkv * Kd];  // w_qkv^T hi [N][K]
__device__ __align__(1024) __half g_wq_l[(size_t)Nqkv * Kd];
__device__ __align__(1024) __half g_wo_h[(size_t)Cc * Kd];    // w_out^T hi [N][K]
__device__ __align__(1024) __half g_wo_l[(size_t)Cc * Kd];
__device__ __align__(1024) __half g_a_h[(size_t)Mtot * Kd];   // attn out hi [M][K]
__device__ __align__(1024) __half g_a_l[(size_t)Mtot * Kd];
// attention operands, per-head layouts
__device__ __align__(1024) __half g_q_h[(size_t)Bb * Hh * Ts * Dh];   // [b,h,t,d] (pre-scaled)
__device__ __align__(1024) __half g_q_l[(size_t)Bb * Hh * Ts * Dh];
__device__ __align__(1024) __half g_k_h[(size_t)Bb * Hh * Ts * Dh];   // [b,h,t,d]
__device__ __align__(1024) __half g_k_l[(size_t)Bb * Hh * Ts * Dh];
__device__ __align__(1024) __half g_vt_h[(size_t)Bb * Hh * Dh * Ts];  // [b,h,d,t]
__device__ __align__(1024) __half g_vt_l[(size_t)Bb * Hh * Dh * Ts];

// ---------------- PTX helpers (sm_80-level, compile for compute_103) --------
__device__ __forceinline__ uint32_t smem_u32(const void* p) {
    uint32_t a;
    asm("{ .reg .u64 t; cvta.to.shared.u64 t, %1; cvt.u32.u64 %0, t; }" : "=r"(a) : "l"(p));
    return a;
}
__device__ __forceinline__ void cpa16(uint32_t dst, const void* src) {
    asm volatile("cp.async.cg.shared.global [%0], [%1], 16;" :: "r"(dst), "l"(src));
}
__device__ __forceinline__ void cp_commit() {
    asm volatile("cp.async.commit_group;" ::: "memory");
}
template<int n>
__device__ __forceinline__ void cp_wait() {
    asm volatile("cp.async.wait_group %0;" :: "n"(n) : "memory");
}
__device__ __forceinline__ void ldsm4(uint32_t* r, uint32_t addr) {
    asm volatile("ldmatrix.sync.aligned.m8n8.x4.shared.b16 {%0,%1,%2,%3}, [%4];"
                 : "=r"(r[0]), "=r"(r[1]), "=r"(r[2]), "=r"(r[3]) : "r"(addr));
}
__device__ __forceinline__ void mma16816(float* d, const uint32_t* a, const uint32_t* b) {
    asm volatile(
        "mma.sync.aligned.m16n8k16.row.col.f32.f16.f16.f32 "
        "{%0,%1,%2,%3}, {%4,%5,%6,%7}, {%8,%9}, {%0,%1,%2,%3};"
        : "+f"(d[0]), "+f"(d[1]), "+f"(d[2]), "+f"(d[3])
        : "r"(a[0]), "r"(a[1]), "r"(a[2]), "r"(a[3]), "r"(b[0]), "r"(b[1]));
}
__device__ __forceinline__ void pack_hilo(float x, float y, uint32_t& h, uint32_t& l) {
    __half2 hh = __floats2half2_rn(x, y);
    float2 hf = __half22float2(hh);
    __half2 ll = __floats2half2_rn(x - hf.x, y - hf.y);
    h = *(uint32_t*)&hh;
    l = *(uint32_t*)&ll;
}

// ---------------------------------------------------------------------------
// conv_A: fp32 [rows,1024] -> hi/lo fp16 row-major (8 elems/thread)
// ---------------------------------------------------------------------------
__global__ __launch_bounds__(256)
void conv_A(const float* __restrict__ src, __half* __restrict__ dh, __half* __restrict__ dl)
{
    size_t u = (size_t)blockIdx.x * 256 + threadIdx.x;
    const float4* p = (const float4*)(src + u * 8);
    float4 f0 = p[0], f1 = p[1];
    float f[8] = {f0.x, f0.y, f0.z, f0.w, f1.x, f1.y, f1.z, f1.w};
    union { __half h[8]; uint4 v; } H, L;
#pragma unroll
    for (int j = 0; j < 8; j++) {
        __half hi = __float2half_rn(f[j]);
        H.h[j] = hi;
        L.h[j] = __float2half_rn(f[j] - __half2float(hi));
    }
    *(uint4*)(dh + u * 8) = H.v;
    *(uint4*)(dl + u * 8) = L.v;
}

// conv_B: fp32 weight [K,N] -> transposed [N][K] hi/lo
__global__ __launch_bounds__(256)
void conv_B(const float* __restrict__ w, __half* __restrict__ dh, __half* __restrict__ dl, int N)
{
    int n  = blockIdx.x * 256 + threadIdx.x;
    int k0 = blockIdx.y * 8;
    union { __half h[8]; uint4 v; } H, L;
#pragma unroll
    for (int j = 0; j < 8; j++) {
        float f = w[(size_t)(k0 + j) * N + n];
        __half hi = __float2half_rn(f);
        H.h[j] = hi;
        L.h[j] = __float2half_rn(f - __half2float(hi));
    }
    *(uint4*)(dh + (size_t)n * Kd + k0) = H.v;
    *(uint4*)(dl + (size_t)n * Kd + k0) = L.v;
}

// ---------------------------------------------------------------------------
// conv_qkv: g_qkv fp32 -> Q(hi/lo, pre-scaled) [b,h,t,d], K(hi/lo) [b,h,t,d],
//           V^T(hi/lo) [b,h,d,t].  grid (Ts/64, Hh, Bb), 256 thr.
// ---------------------------------------------------------------------------
__global__ __launch_bounds__(256)
void conv_qkv()
{
    __shared__ float vs[64][65];
    const int b = blockIdx.z, h = blockIdx.y, t0 = blockIdx.x * 64;
    const int tid = threadIdx.x;
    const int tl = tid >> 2;
    const int d0 = (tid & 3) * 16;
    const float* src = g_qkv + ((size_t)b * Ts + t0 + tl) * Nqkv + h * Dh + d0;
    const size_t qk_off = ((size_t)(b * Hh + h) * Ts + t0 + tl) * Dh + d0;

    union { __half hh[16]; uint4 v[2]; } QH_, QL_, KH_, KL_;
#pragma unroll
    for (int j = 0; j < 16; j++) {
        float q = src[j] * 0.125f;
        __half qh = __float2half_rn(q);
        QH_.hh[j] = qh;
        QL_.hh[j] = __float2half_rn(q - __half2float(qh));
        float k = src[Cc + j];
        __half kh = __float2half_rn(k);
        KH_.hh[j] = kh;
        KL_.hh[j] = __float2half_rn(k - __half2float(kh));
        vs[tl][d0 + j] = src[2 * Cc + j];
    }
    *(uint4*)(g_q_h + qk_off) = QH_.v[0]; *(uint4*)(g_q_h + qk_off + 8) = QH_.v[1];
    *(uint4*)(g_q_l + qk_off) = QL_.v[0]; *(uint4*)(g_q_l + qk_off + 8) = QL_.v[1];
    *(uint4*)(g_k_h + qk_off) = KH_.v[0]; *(uint4*)(g_k_h + qk_off + 8) = KH_.v[1];
    *(uint4*)(g_k_l + qk_off) = KL_.v[0]; *(uint4*)(g_k_l + qk_off + 8) = KL_.v[1];
    __syncthreads();

    const int d  = tid >> 2;
    const int tg = (tid & 3) * 16;
    union { __half hh[16]; uint4 v[2]; } VH_, VL_;
#pragma unroll
    for (int j = 0; j < 16; j++) {
        float f = vs[tg + j][d];
        __half hi = __float2half_rn(f);
        VH_.hh[j] = hi;
        VL_.hh[j] = __float2half_rn(f - __half2float(hi));
    }
    size_t vt_off = ((size_t)(b * Hh + h) * Dh + d) * Ts + t0 + tg;
    *(uint4*)(g_vt_h + vt_off) = VH_.v[0]; *(uint4*)(g_vt_h + vt_off + 8) = VH_.v[1];
    *(uint4*)(g_vt_l + vt_off) = VL_.v[0]; *(uint4*)(g_vt_l + vt_off + 8) = VL_.v[1];
}

// ---------------------------------------------------------------------------
// HMMA GEMM v4 (resubmit of R13 — audited safe; R13 bench was an infra flake):
// single __syncthreads per chunk.
//   per chunk i: cp_wait(group i) -> barrier -> issue prefetch i+2 -> compute.
// WAR safety: load i+2 hits stage (i+2)%3, last read at chunk i-1; every warp
// is past this iter's barrier only after finishing chunk i-1's compute.
// ---------------------------------------------------------------------------
constexpr int BK2      = 32;
constexpr int T2_BYTES = 128 * BK2 * 2;     // 8 KB per operand tile
constexpr int S2_BYTES = 4 * T2_BYTES;      // 32 KB per stage
constexpr int NST      = 3;
constexpr int GEMM_SMEM = NST * S2_BYTES;   // 98304
constexpr int NCH2     = Kd / BK2;          // 32 chunks

__global__ __launch_bounds__(256, 2)
void gemm_hmma(const __half* __restrict__ Ah, const __half* __restrict__ Al,
               const __half* __restrict__ Bh, const __half* __restrict__ Bl,
               const float* __restrict__ bias, float* __restrict__ C, int N)
{
    extern __shared__ char smem_raw[];
    const uint32_t sbase = smem_u32(smem_raw);

    const int tid  = threadIdx.x;
    const int lane = tid & 31;
    const int wid  = tid >> 5;
    const int wm   = wid >> 2;
    const int wn   = wid & 3;
    const int bm   = blockIdx.y, bn = blockIdx.x;

    const int cr  = tid >> 1;
    const int cu0 = (tid & 1) * 2;
    const int csw = (cr >> 1) & 3;
    const __half* srcs[4] = {
        Ah + (size_t)(bm * 128 + cr) * Kd,
        Al + (size_t)(bm * 128 + cr) * Kd,
        Bh + (size_t)(bn * 128 + cr) * Kd,
        Bl + (size_t)(bn * 128 + cr) * Kd
    };
    const uint32_t dstrow = (uint32_t)cr * 64;

    auto load_stage = [&](int s, int ch) {
        uint32_t sb = sbase + s * S2_BYTES;
#pragma unroll
        for (int t = 0; t < 4; t++) {
            const __half* src = srcs[t] + ch * BK2;
            uint32_t tb = sb + t * T2_BYTES + dstrow;
#pragma unroll
            for (int j = 0; j < 2; j++) {
                int u = cu0 + j;
                cpa16(tb + ((u ^ csw) * 16), src + u * 8);
            }
        }
    };

    float acc[4][4][4];
#pragma unroll
    for (int i = 0; i < 4; i++)
#pragma unroll
        for (int j = 0; j < 4; j++)
#pragma unroll
            for (int k = 0; k < 4; k++) acc[i][j][k] = 0.f;

    const int rA = lane & 15, kg = lane >> 4;
    uint32_t arow[4], brow[2];
    int asw[4], bsw[2];
#pragma unroll
    for (int mi = 0; mi < 4; mi++) {
        int r = wm * 64 + mi * 16 + rA;
        arow[mi] = (uint32_t)r * 64; asw[mi] = (r >> 1) & 3;
    }
#pragma unroll
    for (int np = 0; np < 2; np++) {
        int r = wn * 32 + np * 16 + rA;
        brow[np] = (uint32_t)r * 64; bsw[np] = (r >> 1) & 3;
    }

    load_stage(0, 0); cp_commit();
    load_stage(1, 1); cp_commit();

    for (int i = 0; i < NCH2; i++) {
        if (i + 1 < NCH2) cp_wait<1>(); else cp_wait<0>();
        __syncthreads();
        if (i + 2 < NCH2) { load_stage((i + 2) % NST, i + 2); cp_commit(); }

        uint32_t sb = sbase + (i % NST) * S2_BYTES;
#pragma unroll
        for (int ks = 0; ks < 2; ks++) {
            int kb = ks * 2 + kg;
            uint32_t bh[4][2], bl[4][2];
#pragma unroll
            for (int np = 0; np < 2; np++) {
                uint32_t off = brow[np] + (uint32_t)((kb ^ bsw[np]) * 16);
                uint32_t t[4];
                ldsm4(t, sb + 2 * T2_BYTES + off);
                bh[2*np][0] = t[0]; bh[2*np+1][0] = t[1];
                bh[2*np][1] = t[2]; bh[2*np+1][1] = t[3];
                ldsm4(t, sb + 3 * T2_BYTES + off);
                bl[2*np][0] = t[0]; bl[2*np+1][0] = t[1];
                bl[2*np][1] = t[2]; bl[2*np+1][1] = t[3];
            }
#pragma unroll
            for (int mi = 0; mi < 4; mi++) {
                uint32_t off = arow[mi] + (uint32_t)((kb ^ asw[mi]) * 16);
                uint32_t ah[4], al[4];
                ldsm4(ah, sb + off);
                ldsm4(al, sb + T2_BYTES + off);
#pragma unroll
                for (int ni = 0; ni < 4; ni++) mma16816(acc[mi][ni], ah, bh[ni]);
#pragma unroll
                for (int ni = 0; ni < 4; ni++) mma16816(acc[mi][ni], ah, bl[ni]);
#pragma unroll
                for (int ni = 0; ni < 4; ni++) mma16816(acc[mi][ni], al, bh[ni]);
            }
        }
        // no trailing barrier: next iter's single barrier closes the WAR window
    }

    const int er = lane >> 2, ec = (lane & 3) * 2;
#pragma unroll
    for (int mi = 0; mi < 4; mi++) {
        size_t r0 = (size_t)bm * 128 + wm * 64 + mi * 16 + er;
#pragma unroll
        for (int ni = 0; ni < 4; ni++) {
            int c = bn * 128 + wn * 32 + ni * 8 + ec;
            float2 bv = *(const float2*)(bias + c);
            float2 o0 = { acc[mi][ni][0] + bv.x, acc[mi][ni][1] + bv.y };
            float2 o1 = { acc[mi][ni][2] + bv.x, acc[mi][ni][3] + bv.y };
            *(float2*)(C + r0 * N + c)       = o0;
            *(float2*)(C + (r0 + 8) * N + c) = o1;
        }
    }
}

// ---------------------------------------------------------------------------
// flash_hmma: known-good R10 version (256 threads, 128 q-rows) — unchanged.
// ---------------------------------------------------------------------------
constexpr int ATT_SMEM = 32768 + 2 * 32768;  // 98304

__global__ __launch_bounds__(256, 1)
void flash_hmma()
{
    extern __shared__ char sm[];
    const uint32_t sb  = smem_u32(sm);
    const uint32_t QHs = sb, QLs = sb + 16384;

    const int tid = threadIdx.x, lane = tid & 31, wq = tid >> 5;
    const int qt = blockIdx.x, h = blockIdx.y, b = blockIdx.z;
    const int q0 = qt * 128;
    const int ktmax = 2 * qt + 1;

    const size_t bh = (size_t)(b * Hh + h);
    const __half* Qh = g_q_h + (bh * Ts + q0) * Dh;
    const __half* Ql = g_q_l + (bh * Ts + q0) * Dh;
    const __half* Kh = g_k_h + bh * Ts * Dh;
    const __half* Kl = g_k_l + bh * Ts * Dh;
    const __half* Vh = g_vt_h + bh * Dh * Ts;
    const __half* Vl = g_vt_l + bh * Dh * Ts;

    {
        int qr = tid >> 1, u0 = (tid & 1) * 4;
#pragma unroll
        for (int j = 0; j < 4; j++) {
            int u = u0 + j; int ph = u ^ (qr & 7);
            cpa16(QHs + qr * 128 + ph * 16, Qh + (size_t)qr * 64 + u * 8);
            cpa16(QLs + qr * 128 + ph * 16, Ql + (size_t)qr * 64 + u * 8);
        }
    }
    const int kr = tid >> 2, ku0 = (tid & 3) * 2;
    auto load_kv = [&](int s, int kt) {
        uint32_t base = sb + 32768 + s * 32768;
        int k0 = kt * 64;
#pragma unroll
        for (int j = 0; j < 2; j++) {
            int u = ku0 + j; int ph = u ^ (kr & 7);
            uint32_t o = kr * 128 + ph * 16;
            cpa16(base + o,         Kh + (size_t)(k0 + kr) * 64 + u * 8);
            cpa16(base + 8192 + o,  Kl + (size_t)(k0 + kr) * 64 + u * 8);
            cpa16(base + 16384 + o, Vh + (size_t)kr * Ts + k0 + u * 8);
            cpa16(base + 24576 + o, Vl + (size_t)kr * Ts + k0 + u * 8);
        }
    };
    load_kv(0, 0);
    cp_commit();
    load_kv(1, 1);
    cp_commit();
    cp_wait<1>();
    __syncthreads();

    uint32_t qfh[4][4], qfl[4][4];
    {
        int row = wq * 16 + (lane & 15);
#pragma unroll
        for (int ks = 0; ks < 4; ks++) {
            int u = ks * 2 + (lane >> 4); int ph = u ^ (row & 7);
            uint32_t o = row * 128 + ph * 16;
            ldsm4(qfh[ks], QHs + o);
            ldsm4(qfl[ks], QLs + o);
        }
    }

    float m0 = -1e30f, m1 = -1e30f, l0 = 0.f, l1 = 0.f;
    float oacc[8][4];
#pragma unroll
    for (int i = 0; i < 8; i++)
#pragma unroll
        for (int j = 0; j < 4; j++) oacc[i][j] = 0.f;

    const int rg0 = q0 + wq * 16 + (lane >> 2);

    for (int kt = 0; kt <= ktmax; kt++) {
        if (kt > 0) {
            if (kt + 1 <= ktmax) { load_kv((kt + 1) & 1, kt + 1); cp_commit(); cp_wait<1>(); }
            else                 { cp_wait<0>(); }
            __syncthreads();
        }
        const uint32_t kb = sb + 32768 + (kt & 1) * 32768;
        const int k0 = kt * 64;

        if (k0 <= q0 + wq * 16 + 15) {
            float sacc[8][4];
#pragma unroll
            for (int i = 0; i < 8; i++)
#pragma unroll
                for (int j = 0; j < 4; j++) sacc[i][j] = 0.f;

#pragma unroll
            for (int ks = 0; ks < 4; ks++) {
#pragma unroll
                for (int np = 0; np < 4; np++) {
                    int row = np * 16 + (lane & 15);
                    int u = ks * 2 + (lane >> 4); int ph = u ^ (row & 7);
                    uint32_t o = row * 128 + ph * 16;
                    uint32_t th[4], tl[4];
                    ldsm4(th, kb + o);
                    ldsm4(tl, kb + 8192 + o);
                    uint32_t beh[2] = {th[0], th[2]}, boh[2] = {th[1], th[3]};
                    uint32_t bel[2] = {tl[0], tl[2]}, bol[2] = {tl[1], tl[3]};
                    mma16816(sacc[2*np],   qfh[ks], beh);
                    mma16816(sacc[2*np],   qfh[ks], bel);
                    mma16816(sacc[2*np],   qfl[ks], beh);
                    mma16816(sacc[2*np+1], qfh[ks], boh);
                    mma16816(sacc[2*np+1], qfh[ks], bol);
                    mma16816(sacc[2*np+1], qfl[ks], boh);
                }
            }
            if (k0 + 63 > q0 + wq * 16) {
#pragma unroll
                for (int nt = 0; nt < 8; nt++) {
                    int cg = k0 + nt * 8 + (lane & 3) * 2;
                    if (cg     > rg0)     sacc[nt][0] = -1e30f;
                    if (cg + 1 > rg0)     sacc[nt][1] = -1e30f;
                    if (cg     > rg0 + 8) sacc[nt][2] = -1e30f;
                    if (cg + 1 > rg0 + 8) sacc[nt][3] = -1e30f;
                }
            }
            float mx0 = -1e30f, mx1 = -1e30f;
#pragma unroll
            for (int nt = 0; nt < 8; nt++) {
                mx0 = fmaxf(mx0, fmaxf(sacc[nt][0], sacc[nt][1]));
                mx1 = fmaxf(mx1, fmaxf(sacc[nt][2], sacc[nt][3]));
            }
            mx0 = fmaxf(mx0, __shfl_xor_sync(0xffffffffu, mx0, 1));
            mx0 = fmaxf(mx0, __shfl_xor_sync(0xffffffffu, mx0, 2));
            mx1 = fmaxf(mx1, __shfl_xor_sync(0xffffffffu, mx1, 1));
            mx1 = fmaxf(mx1, __shfl_xor_sync(0xffffffffu, mx1, 2));
            float mn0 = fmaxf(m0, mx0), mn1 = fmaxf(m1, mx1);
            float f0 = __expf(m0 - mn0), f1 = __expf(m1 - mn1);
            m0 = mn0; m1 = mn1;
            float rs0 = 0.f, rs1 = 0.f;
#pragma unroll
            for (int nt = 0; nt < 8; nt++) {
                sacc[nt][0] = __expf(sacc[nt][0] - mn0); rs0 += sacc[nt][0];
                sacc[nt][1] = __expf(sacc[nt][1] - mn0); rs0 += sacc[nt][1];
                sacc[nt][2] = __expf(sacc[nt][2] - mn1); rs1 += sacc[nt][2];
                sacc[nt][3] = __expf(sacc[nt][3] - mn1); rs1 += sacc[nt][3];
            }
            rs0 += __shfl_xor_sync(0xffffffffu, rs0, 1);
            rs0 += __shfl_xor_sync(0xffffffffu, rs0, 2);
            rs1 += __shfl_xor_sync(0xffffffffu, rs1, 1);
            rs1 += __shfl_xor_sync(0xffffffffu, rs1, 2);
            l0 = l0 * f0 + rs0;
            l1 = l1 * f1 + rs1;
#pragma unroll
            for (int dt = 0; dt < 8; dt++) {
                oacc[dt][0] *= f0; oacc[dt][1] *= f0;
                oacc[dt][2] *= f1; oacc[dt][3] *= f1;
            }
#pragma unroll
            for (int ks = 0; ks < 4; ks++) {
                uint32_t pah[4], pal[4];
                pack_hilo(sacc[2*ks][0],   sacc[2*ks][1],   pah[0], pal[0]);
                pack_hilo(sacc[2*ks][2],   sacc[2*ks][3],   pah[1], pal[1]);
                pack_hilo(sacc[2*ks+1][0], sacc[2*ks+1][1], pah[2], pal[2]);
                pack_hilo(sacc[2*ks+1][2], sacc[2*ks+1][3], pah[3], pal[3]);
#pragma unroll
                for (int dp = 0; dp < 4; dp++) {
                    int row = dp * 16 + (lane & 15);
                    int u = ks * 2 + (lane >> 4); int ph = u ^ (row & 7);
                    uint32_t o = row * 128 + ph * 16;
                    uint32_t th[4], tl[4];
                    ldsm4(th, kb + 16384 + o);
                    ldsm4(tl, kb + 24576 + o);
                    uint32_t beh[2] = {th[0], th[2]}, boh[2] = {th[1], th[3]};
                    uint32_t bel[2] = {tl[0], tl[2]}, bol[2] = {tl[1], tl[3]};
                    mma16816(oacc[2*dp],   pah, beh);
                    mma16816(oacc[2*dp],   pah, bel);
                    mma16816(oacc[2*dp],   pal, beh);
                    mma16816(oacc[2*dp+1], pah, boh);
                    mma16816(oacc[2*dp+1], pah, bol);
                    mma16816(oacc[2*dp+1], pal, boh);
                }
            }
        }
        __syncthreads();
    }

    float i0 = 1.f / l0, i1 = 1.f / l1;
#pragma unroll
    for (int dt = 0; dt < 8; dt++) {
        int c = h * Dh + dt * 8 + (lane & 3) * 2;
        uint32_t hh, ll;
        pack_hilo(oacc[dt][0] * i0, oacc[dt][1] * i0, hh, ll);
        size_t off = ((size_t)b * Ts + rg0) * Cc + c;
        *(uint32_t*)(g_a_h + off) = hh;
        *(uint32_t*)(g_a_l + off) = ll;
        pack_hilo(oacc[dt][2] * i1, oacc[dt][3] * i1, hh, ll);
        off = ((size_t)b * Ts + rg0 + 8) * Cc + c;
        *(uint32_t*)(g_a_h + off) = hh;
        *(uint32_t*)(g_a_l + off) = ll;
    }
}

// ---------------------------------------------------------------------------
// Launch (graph-capturable: kernels only)
// ---------------------------------------------------------------------------
extern "C" void kernel_launch(void* const* d_in, const int* in_sizes, int n_in,
                              void* d_out, int out_size)
{
    const float* x     = (const float*)d_in[0];
    const float* w_qkv = (const float*)d_in[1];
    const float* b_qkv = (const float*)d_in[2];
    const float* w_out = (const float*)d_in[3];
    const float* b_out = (const float*)d_in[4];
    float* out = (float*)d_out;

    float* qkv_ptr;
    __half *xh, *xl, *wqh, *wql, *woh, *wol, *ah, *al;
    cudaGetSymbolAddress((void**)&qkv_ptr, g_qkv);
    cudaGetSymbolAddress((void**)&xh,  g_x_h);  cudaGetSymbolAddress((void**)&xl,  g_x_l);
    cudaGetSymbolAddress((void**)&wqh, g_wq_h); cudaGetSymbolAddress((void**)&wql, g_wq_l);
    cudaGetSymbolAddress((void**)&woh, g_wo_h); cudaGetSymbolAddress((void**)&wol, g_wo_l);
    cudaGetSymbolAddress((void**)&ah,  g_a_h);  cudaGetSymbolAddress((void**)&al,  g_a_l);

    cudaFuncSetAttribute(gemm_hmma, cudaFuncAttributeMaxDynamicSharedMemorySize, GEMM_SMEM);
    cudaFuncSetAttribute(flash_hmma, cudaFuncAttributeMaxDynamicSharedMemorySize, ATT_SMEM);

    // 0) operand conversion
    conv_A<<<(int)(((size_t)Mtot * Kd / 8) / 256), 256>>>(x, xh, xl);
    conv_B<<<dim3(Nqkv / 256, Kd / 8), 256>>>(w_qkv, wqh, wql, Nqkv);
    conv_B<<<dim3(Cc / 256, Kd / 8), 256>>>(w_out, woh, wol, Cc);

    // 1) QKV projection (HMMA)
    gemm_hmma<<<dim3(Nqkv / 128, Mtot / 128), 256, GEMM_SMEM>>>(
        xh, xl, wqh, wql, b_qkv, qkv_ptr, Nqkv);

    // 2) per-head hi/lo conversion + V transpose
    conv_qkv<<<dim3(Ts / 64, Hh, Bb), 256>>>();

    // 3) causal flash attention (HMMA), 128 q-rows/block
    flash_hmma<<<dim3(Ts / 128, Hh, Bb), 256, ATT_SMEM>>>();

    // 4) output projection (HMMA)
    gemm_hmma<<<dim3(Cc / 128, Mtot / 128), 256, GEMM_SMEM>>>(
        ah, al, woh, wol, b_out, out, Cc);
}